// round 2
// baseline (speedup 1.0000x reference)
#include <cuda_runtime.h>

#define N_NODES 50000
#define N_EDGES 500000
#define N_GRAPHS 2000
#define HID 145
#define PITCH 148          // pad to 16B multiple (148*4 = 592 = 37 * 16)
#define WPITCH 160         // Ws shared pitch: col_t + 32*4 <= 159
#define HID2 72
#define N_LAYERS 4
#define EPS 1e-5f

// ---- scratch (static device globals; no runtime allocation) ----
__device__ __align__(16) float  g_h  [(size_t)N_NODES * PITCH];
__device__ __align__(16) float  g_hw [(size_t)N_NODES * PITCH];
__device__ __align__(16) float  g_agg[(size_t)N_NODES * PITCH];
__device__ float  g_dis[N_NODES];
__device__ double g_stats[2 * PITCH];
__device__ float  g_bnA[PITCH];
__device__ float  g_bnB[PITCH];

// ---------------- degree / normalization ----------------
__global__ void k_deg_init() {
    int i = blockIdx.x * blockDim.x + threadIdx.x;
    if (i < N_NODES) g_dis[i] = 1.0f;   // self loop contributes 1 to deg
}

__global__ void k_deg_count(const int* __restrict__ ei) {
    int e = blockIdx.x * blockDim.x + threadIdx.x;
    if (e < N_EDGES) atomicAdd(&g_dis[ei[N_EDGES + e]], 1.0f);  // target = col
}

__global__ void k_dis() {
    int i = blockIdx.x * blockDim.x + threadIdx.x;
    if (i < N_NODES) g_dis[i] = rsqrtf(g_dis[i]);   // deg >= 1 always
}

// ---------------- embedding gather ----------------
__global__ void k_embed(const int* __restrict__ x, const float* __restrict__ emb) {
    int idx = blockIdx.x * blockDim.x + threadIdx.x;
    if (idx >= N_NODES * PITCH) return;
    int i = idx / PITCH, c = idx - i * PITCH;
    g_h[idx] = (c < HID) ? emb[x[i] * HID + c] : 0.0f;
}

// ---------------- GEMM: hw = h @ Wc[l], M=50000, N=K=145 ----------------
// Block: 32 rows x 160 cols (145 live), 256 threads, K tiled by 32.
__global__ void k_gemm(const float* __restrict__ Wl) {
    __shared__ float As[32 * PITCH];
    __shared__ float Ws[32 * WPITCH];
    const int tid  = threadIdx.x;
    const int row0 = blockIdx.x * 32;

    for (int i = tid; i < 32 * PITCH; i += 256) {
        int r = row0 + i / PITCH;
        As[i] = (r < N_NODES) ? g_h[(size_t)row0 * PITCH + i] : 0.0f;
    }

    const int col_t = tid & 31;     // cols col_t + 32*j, j=0..4 (0..159)
    const int row_t = tid >> 5;     // rows row_t*4 .. +3
    float acc[4][5];
#pragma unroll
    for (int r = 0; r < 4; r++)
#pragma unroll
        for (int j = 0; j < 5; j++) acc[r][j] = 0.0f;

    for (int kt = 0; kt < HID; kt += 32) {
        const int kmax = (HID - kt) < 32 ? (HID - kt) : 32;
        __syncthreads();
        for (int i = tid; i < 32 * WPITCH; i += 256) {
            int kk = i / WPITCH, c = i - kk * WPITCH;
            Ws[i] = (kk < kmax && c < HID) ? Wl[(kt + kk) * HID + c] : 0.0f;
        }
        __syncthreads();
        for (int k = 0; k < kmax; k++) {
            float a0 = As[(row_t * 4 + 0) * PITCH + kt + k];
            float a1 = As[(row_t * 4 + 1) * PITCH + kt + k];
            float a2 = As[(row_t * 4 + 2) * PITCH + kt + k];
            float a3 = As[(row_t * 4 + 3) * PITCH + kt + k];
#pragma unroll
            for (int j = 0; j < 5; j++) {
                float b = Ws[k * WPITCH + col_t + 32 * j];
                acc[0][j] += a0 * b;
                acc[1][j] += a1 * b;
                acc[2][j] += a2 * b;
                acc[3][j] += a3 * b;
            }
        }
    }

#pragma unroll
    for (int rr = 0; rr < 4; rr++) {
        int r = row0 + row_t * 4 + rr;
        if (r >= N_NODES) continue;
#pragma unroll
        for (int j = 0; j < 5; j++) {
            int c = col_t + 32 * j;
            if (c < PITCH) g_hw[(size_t)r * PITCH + c] = acc[rr][j];
        }
    }
}

// ---------------- agg init: bias + self-loop term; zero stats ----------------
__global__ void k_init_agg(const float* __restrict__ bcl) {
    int idx = blockIdx.x * blockDim.x + threadIdx.x;
    if (idx < 2 * PITCH) g_stats[idx] = 0.0;
    if (idx >= N_NODES * PITCH) return;
    int i = idx / PITCH, c = idx - i * PITCH;
    float d = g_dis[i];
    float sw = d * d;                         // self-loop weight = 1/deg
    float b = (c < HID) ? bcl[c] : 0.0f;
    g_agg[idx] = b + sw * g_hw[idx];
}

// ---------------- edge scatter: warp per edge, vector atomics ----------------
__global__ void k_scatter(const int* __restrict__ ei) {
    int gtid = blockIdx.x * blockDim.x + threadIdx.x;
    int e    = gtid >> 5;
    int lane = gtid & 31;
    if (e >= N_EDGES) return;
    int r = ei[e];
    int c = ei[N_EDGES + e];
    float w = g_dis[r] * g_dis[c];
    const float4* src = (const float4*)g_hw  + (size_t)r * (PITCH / 4);
    float4*       dst = (float4*)g_agg + (size_t)c * (PITCH / 4);

    float4 v = src[lane];
    asm volatile("red.global.add.v4.f32 [%0], {%1,%2,%3,%4};"
                 :: "l"(dst + lane), "f"(v.x * w), "f"(v.y * w), "f"(v.z * w), "f"(v.w * w)
                 : "memory");
    if (lane < (PITCH / 4) - 32) {            // lanes 0..4 -> chunks 32..36
        float4 v2 = src[32 + lane];
        asm volatile("red.global.add.v4.f32 [%0], {%1,%2,%3,%4};"
                     :: "l"(dst + 32 + lane), "f"(v2.x * w), "f"(v2.y * w), "f"(v2.z * w), "f"(v2.w * w)
                     : "memory");
    }
}

// ---------------- batchnorm stats (double partials + double atomics) ----------
#define STAT_BLOCKS 250
#define ROWS_PER_STAT ((N_NODES + STAT_BLOCKS - 1) / STAT_BLOCKS)
__global__ void k_stats() {
    int c = threadIdx.x;
    if (c >= HID) return;
    int r0 = blockIdx.x * ROWS_PER_STAT;
    int r1 = r0 + ROWS_PER_STAT; if (r1 > N_NODES) r1 = N_NODES;
    double s1 = 0.0, s2 = 0.0;
    for (int r = r0; r < r1; r++) {
        double v = (double)g_agg[(size_t)r * PITCH + c];
        s1 += v; s2 += v * v;
    }
    atomicAdd(&g_stats[c], s1);
    atomicAdd(&g_stats[PITCH + c], s2);
}

__global__ void k_bnab(const float* __restrict__ gammal, const float* __restrict__ betal) {
    int c = threadIdx.x;
    if (c >= PITCH) return;
    if (c < HID) {
        double mu  = g_stats[c] / (double)N_NODES;
        double var = g_stats[PITCH + c] / (double)N_NODES - mu * mu;
        if (var < 0.0) var = 0.0;
        float a = gammal[c] * rsqrtf((float)var + EPS);
        g_bnA[c] = a;
        g_bnB[c] = betal[c] - (float)mu * a;
    } else {
        g_bnA[c] = 0.0f;
        g_bnB[c] = 0.0f;
    }
}

// ---------------- BN apply + ReLU + residual (in place on g_h) ----------------
__global__ void k_apply() {
    int idx = blockIdx.x * blockDim.x + threadIdx.x;
    if (idx >= N_NODES * PITCH) return;
    int c = idx % PITCH;
    float v = fmaxf(g_agg[idx] * g_bnA[c] + g_bnB[c], 0.0f) + g_h[idx];
    g_h[idx] = v;
}

// ---------------- global mean pool + MLP head, one block per graph -----------
__global__ void k_pool(const int* __restrict__ batch,
                       const float* __restrict__ W1, const float* __restrict__ b1,
                       const float* __restrict__ W2, const float* __restrict__ b2,
                       float* __restrict__ out) {
    const int g   = blockIdx.x;
    const int tid = threadIdx.x;
    __shared__ float hg[HID];
    __shared__ float p[HID2];

    // lower bounds in sorted batch_idx (all threads redundantly; cheap)
    int lo, hi;
    { int a = 0, b = N_NODES;
      while (a < b) { int m = (a + b) >> 1; if (batch[m] < g) a = m + 1; else b = m; }
      lo = a; }
    { int a = lo, b = N_NODES;
      while (a < b) { int m = (a + b) >> 1; if (batch[m] < g + 1) a = m + 1; else b = m; }
      hi = a; }
    int cnt = hi - lo;
    float inv = 1.0f / (float)(cnt > 1 ? cnt : 1);

    if (tid < HID) {
        float s = 0.0f;
        for (int r = lo; r < hi; r++) s += g_h[(size_t)r * PITCH + tid];
        hg[tid] = s * inv;
    }
    __syncthreads();
    if (tid < HID2) {
        float s = b1[tid];
        for (int k = 0; k < HID; k++) s += hg[k] * W1[k * HID2 + tid];
        p[tid] = fmaxf(s, 0.0f) * W2[tid];
    }
    __syncthreads();
    if (tid == 0) {
        float s = b2[0];
        for (int j = 0; j < HID2; j++) s += p[j];
        out[g] = s;
    }
}

// ---------------- launch ----------------
extern "C" void kernel_launch(void* const* d_in, const int* in_sizes, int n_in,
                              void* d_out, int out_size) {
    const int*   x     = (const int*)  d_in[0];
    const int*   ei    = (const int*)  d_in[1];
    const int*   batch = (const int*)  d_in[2];
    const float* emb   = (const float*)d_in[3];
    const float* Wc    = (const float*)d_in[4];
    const float* bc    = (const float*)d_in[5];
    const float* gamma = (const float*)d_in[6];
    const float* beta  = (const float*)d_in[7];
    const float* W1    = (const float*)d_in[8];
    const float* b1    = (const float*)d_in[9];
    const float* W2    = (const float*)d_in[10];
    const float* b2    = (const float*)d_in[11];
    float* out = (float*)d_out;

    const int elemBlocks = (N_NODES * PITCH + 255) / 256;

    k_deg_init <<<(N_NODES + 255) / 256, 256>>>();
    k_deg_count<<<(N_EDGES + 255) / 256, 256>>>(ei);
    k_dis      <<<(N_NODES + 255) / 256, 256>>>();
    k_embed    <<<elemBlocks, 256>>>(x, emb);

    for (int l = 0; l < N_LAYERS; l++) {
        k_gemm    <<<(N_NODES + 31) / 32, 256>>>(Wc + (size_t)l * HID * HID);
        k_init_agg<<<elemBlocks, 256>>>(bc + l * HID);
        k_scatter <<<(N_EDGES * 32 + 255) / 256, 256>>>(ei);
        k_stats   <<<STAT_BLOCKS, 160>>>();
        k_bnab    <<<1, 160>>>(gamma + l * HID, beta + l * HID);
        k_apply   <<<elemBlocks, 256>>>();
    }

    k_pool<<<N_GRAPHS, 160>>>(batch, W1, b1, W2, b2, out);
}

// round 4
// speedup vs baseline: 1.1747x; 1.1747x over previous
#include <cuda_runtime.h>

#define N_NODES 50000
#define N_EDGES 500000
#define N_GRAPHS 2000
#define HID 145
#define PITCH 148          // row pitch (16B multiple: 148*4 = 592)
#define WSP 160            // Ws shared pitch: 80 col-pairs
#define HID2 72
#define N_LAYERS 4
#define EPS 1e-5f
#define TILE_M 64

// ---- scratch (static device globals; +64 pad on g_h for overhung tile loads) ----
__device__ __align__(16) float  g_h  [(size_t)N_NODES * PITCH + 64];
__device__ __align__(16) float  g_hw [(size_t)N_NODES * PITCH];
__device__ __align__(16) float  g_agg[(size_t)N_NODES * PITCH];
__device__ float  g_dis[N_NODES];
__device__ double g_stats[2 * PITCH];
__device__ float  g_bnA[PITCH];
__device__ float  g_bnB[PITCH];

// packed f32x2 FMA (ptxas never auto-fuses this; PTX-only)
__device__ __forceinline__ float2 ffma2(float2 a, float2 b, float2 c) {
    unsigned long long ua, ub, uc, ud;
    ua = *reinterpret_cast<unsigned long long*>(&a);
    ub = *reinterpret_cast<unsigned long long*>(&b);
    uc = *reinterpret_cast<unsigned long long*>(&c);
    asm("fma.rn.f32x2 %0, %1, %2, %3;" : "=l"(ud) : "l"(ua), "l"(ub), "l"(uc));
    return *reinterpret_cast<float2*>(&ud);
}

// ---------------- degree / normalization ----------------
__global__ void k_deg_init() {
    int i = blockIdx.x * blockDim.x + threadIdx.x;
    if (i < N_NODES) g_dis[i] = 1.0f;   // self loop contributes 1 to deg
}

__global__ void k_deg_count(const int* __restrict__ ei) {
    int e = blockIdx.x * blockDim.x + threadIdx.x;
    if (e < N_EDGES) atomicAdd(&g_dis[ei[N_EDGES + e]], 1.0f);  // target = col
}

__global__ void k_dis() {
    int i = blockIdx.x * blockDim.x + threadIdx.x;
    if (i < N_NODES) g_dis[i] = rsqrtf(g_dis[i]);   // deg >= 1 always
}

// ---------------- embedding gather ----------------
__global__ void k_embed(const int* __restrict__ x, const float* __restrict__ emb) {
    int idx = blockIdx.x * blockDim.x + threadIdx.x;
    if (idx >= N_NODES * PITCH) return;
    int i = idx / PITCH, c = idx - i * PITCH;
    g_h[idx] = (c < HID) ? emb[x[i] * HID + c] : 0.0f;
}

// ---------------- GEMM + fused agg-init ----------------
// hw = h @ Wc[l]; agg = bc[l] + (1/deg) * hw   (self-loop term)
// Block: 64 rows x 160 cols, 256 threads = 16 col-threads x 16 row-threads.
// Thread: 4 rows x 5 col-pairs, f32x2 accumulators. K tiled by 32.
__global__ void __launch_bounds__(256) k_gemm(const float* __restrict__ Wl,
                                              const float* __restrict__ bcl) {
    __shared__ float As[TILE_M * 32];
    __shared__ float Ws[32 * WSP];
    const int tid  = threadIdx.x;
    const int ct   = tid & 15;          // col-pair group
    const int rt   = tid >> 4;          // row group (4 rows each)
    const int row0 = blockIdx.x * TILE_M;

    // zero BN stats for this layer (FULL 2*PITCH range — strided!)
    if (blockIdx.x == 0)
        for (int i = tid; i < 2 * PITCH; i += 256) g_stats[i] = 0.0;

    float2 acc[4][5];
#pragma unroll
    for (int r = 0; r < 4; r++)
#pragma unroll
        for (int j = 0; j < 5; j++) acc[r][j] = make_float2(0.0f, 0.0f);

    for (int kt = 0; kt < HID; kt += 32) {
        __syncthreads();
        // load A tile [64 x 32] via float4 (g_h padded; tail cols annihilated by zero Ws)
#pragma unroll
        for (int q = 0; q < 2; q++) {
            int fi  = tid + 256 * q;        // 0..511 float4 slots
            int row = fi >> 3;
            int kq  = fi & 7;
            float4 v = make_float4(0.f, 0.f, 0.f, 0.f);
            int r = row0 + row;
            if (r < N_NODES)
                v = *(const float4*)&g_h[(size_t)r * PITCH + kt + kq * 4];
            *(float4*)&As[row * 32 + kq * 4] = v;
        }
        // load W tile [32 x 160], zero outside live range
        for (int i = tid; i < 32 * WSP; i += 256) {
            int kk = i / WSP, c = i - kk * WSP;
            int kg = kt + kk;
            Ws[i] = (kg < HID && c < HID) ? Wl[kg * HID + c] : 0.0f;
        }
        __syncthreads();

#pragma unroll 4
        for (int k = 0; k < 32; k++) {
            float2 b[5];
#pragma unroll
            for (int j = 0; j < 5; j++)
                b[j] = *(const float2*)&Ws[k * WSP + 2 * ct + 32 * j];
            float a0 = As[(rt * 4 + 0) * 32 + k];
            float a1 = As[(rt * 4 + 1) * 32 + k];
            float a2 = As[(rt * 4 + 2) * 32 + k];
            float a3 = As[(rt * 4 + 3) * 32 + k];
            float2 p0 = make_float2(a0, a0), p1 = make_float2(a1, a1);
            float2 p2 = make_float2(a2, a2), p3 = make_float2(a3, a3);
#pragma unroll
            for (int j = 0; j < 5; j++) {
                acc[0][j] = ffma2(p0, b[j], acc[0][j]);
                acc[1][j] = ffma2(p1, b[j], acc[1][j]);
                acc[2][j] = ffma2(p2, b[j], acc[2][j]);
                acc[3][j] = ffma2(p3, b[j], acc[3][j]);
            }
        }
    }

#pragma unroll
    for (int rr = 0; rr < 4; rr++) {
        int r = row0 + rt * 4 + rr;
        if (r >= N_NODES) continue;
        float d  = g_dis[r];
        float sw = d * d;                  // self-loop weight = 1/deg
#pragma unroll
        for (int j = 0; j < 5; j++) {
            int c0 = 2 * ct + 32 * j;
            if (c0 >= PITCH) continue;     // c0=146 keeps both cols in-bounds
            float2 v = acc[rr][j];
            *(float2*)&g_hw[(size_t)r * PITCH + c0] = v;
            float2 o;
            o.x = (c0     < HID ? bcl[c0]     : 0.0f) + sw * v.x;
            o.y = (c0 + 1 < HID ? bcl[c0 + 1] : 0.0f) + sw * v.y;
            *(float2*)&g_agg[(size_t)r * PITCH + c0] = o;
        }
    }
}

// ---------------- edge scatter: warp per edge, vector atomics ----------------
__global__ void k_scatter(const int* __restrict__ ei) {
    int gtid = blockIdx.x * blockDim.x + threadIdx.x;
    int e    = gtid >> 5;
    int lane = gtid & 31;
    if (e >= N_EDGES) return;
    int r = ei[e];
    int c = ei[N_EDGES + e];
    float w = g_dis[r] * g_dis[c];
    const float4* src = (const float4*)g_hw  + (size_t)r * (PITCH / 4);
    float4*       dst = (float4*)g_agg + (size_t)c * (PITCH / 4);

    float4 v = src[lane];
    asm volatile("red.global.add.v4.f32 [%0], {%1,%2,%3,%4};"
                 :: "l"(dst + lane), "f"(v.x * w), "f"(v.y * w), "f"(v.z * w), "f"(v.w * w)
                 : "memory");
    if (lane < (PITCH / 4) - 32) {            // lanes 0..4 -> chunks 32..36
        float4 v2 = src[32 + lane];
        asm volatile("red.global.add.v4.f32 [%0], {%1,%2,%3,%4};"
                     :: "l"(dst + 32 + lane), "f"(v2.x * w), "f"(v2.y * w), "f"(v2.z * w), "f"(v2.w * w)
                     : "memory");
    }
}

// ---------------- batchnorm stats (double partials + double atomics) ----------
#define STAT_BLOCKS 250
#define ROWS_PER_STAT ((N_NODES + STAT_BLOCKS - 1) / STAT_BLOCKS)
__global__ void k_stats() {
    int c = threadIdx.x;
    if (c >= HID) return;
    int r0 = blockIdx.x * ROWS_PER_STAT;
    int r1 = r0 + ROWS_PER_STAT; if (r1 > N_NODES) r1 = N_NODES;
    double s1 = 0.0, s2 = 0.0;
    for (int r = r0; r < r1; r++) {
        double v = (double)g_agg[(size_t)r * PITCH + c];
        s1 += v; s2 += v * v;
    }
    atomicAdd(&g_stats[c], s1);
    atomicAdd(&g_stats[PITCH + c], s2);
}

__global__ void k_bnab(const float* __restrict__ gammal, const float* __restrict__ betal) {
    int c = threadIdx.x;
    if (c >= PITCH) return;
    if (c < HID) {
        double mu  = g_stats[c] / (double)N_NODES;
        double var = g_stats[PITCH + c] / (double)N_NODES - mu * mu;
        if (var < 0.0) var = 0.0;
        float a = gammal[c] * rsqrtf((float)var + EPS);
        g_bnA[c] = a;
        g_bnB[c] = betal[c] - (float)mu * a;
    } else {
        g_bnA[c] = 0.0f;
        g_bnB[c] = 0.0f;
    }
}

// ---------------- BN apply + ReLU + residual (in place on g_h) ----------------
__global__ void k_apply() {
    int idx = blockIdx.x * blockDim.x + threadIdx.x;
    if (idx >= N_NODES * PITCH) return;
    int c = idx % PITCH;
    float v = fmaxf(g_agg[idx] * g_bnA[c] + g_bnB[c], 0.0f) + g_h[idx];
    g_h[idx] = v;
}

// ---------------- global mean pool + MLP head, one block per graph -----------
__global__ void k_pool(const int* __restrict__ batch,
                       const float* __restrict__ W1, const float* __restrict__ b1,
                       const float* __restrict__ W2, const float* __restrict__ b2,
                       float* __restrict__ out) {
    const int g   = blockIdx.x;
    const int tid = threadIdx.x;
    __shared__ float hg[HID];
    __shared__ float p[HID2];

    int lo, hi;
    { int a = 0, b = N_NODES;
      while (a < b) { int m = (a + b) >> 1; if (batch[m] < g) a = m + 1; else b = m; }
      lo = a; }
    { int a = lo, b = N_NODES;
      while (a < b) { int m = (a + b) >> 1; if (batch[m] < g + 1) a = m + 1; else b = m; }
      hi = a; }
    int cnt = hi - lo;
    float inv = 1.0f / (float)(cnt > 1 ? cnt : 1);

    if (tid < HID) {
        float s = 0.0f;
        for (int r = lo; r < hi; r++) s += g_h[(size_t)r * PITCH + tid];
        hg[tid] = s * inv;
    }
    __syncthreads();
    if (tid < HID2) {
        float s = b1[tid];
        for (int k = 0; k < HID; k++) s += hg[k] * W1[k * HID2 + tid];
        p[tid] = fmaxf(s, 0.0f) * W2[tid];
    }
    __syncthreads();
    if (tid == 0) {
        float s = b2[0];
        for (int j = 0; j < HID2; j++) s += p[j];
        out[g] = s;
    }
}

// ---------------- launch ----------------
extern "C" void kernel_launch(void* const* d_in, const int* in_sizes, int n_in,
                              void* d_out, int out_size) {
    const int*   x     = (const int*)  d_in[0];
    const int*   ei    = (const int*)  d_in[1];
    const int*   batch = (const int*)  d_in[2];
    const float* emb   = (const float*)d_in[3];
    const float* Wc    = (const float*)d_in[4];
    const float* bc    = (const float*)d_in[5];
    const float* gamma = (const float*)d_in[6];
    const float* beta  = (const float*)d_in[7];
    const float* W1    = (const float*)d_in[8];
    const float* b1    = (const float*)d_in[9];
    const float* W2    = (const float*)d_in[10];
    const float* b2    = (const float*)d_in[11];
    float* out = (float*)d_out;

    const int elemBlocks = (N_NODES * PITCH + 255) / 256;
    const int gemmBlocks = (N_NODES + TILE_M - 1) / TILE_M;

    k_deg_init <<<(N_NODES + 255) / 256, 256>>>();
    k_deg_count<<<(N_EDGES + 255) / 256, 256>>>(ei);
    k_dis      <<<(N_NODES + 255) / 256, 256>>>();
    k_embed    <<<elemBlocks, 256>>>(x, emb);

    for (int l = 0; l < N_LAYERS; l++) {
        k_gemm    <<<gemmBlocks, 256>>>(Wc + (size_t)l * HID * HID, bc + l * HID);
        k_scatter <<<(N_EDGES * 32 + 255) / 256, 256>>>(ei);
        k_stats   <<<STAT_BLOCKS, 160>>>();
        k_bnab    <<<1, 160>>>(gamma + l * HID, beta + l * HID);
        k_apply   <<<elemBlocks, 256>>>();
    }

    k_pool<<<N_GRAPHS, 160>>>(batch, W1, b1, W2, b2, out);
}

// round 5
// speedup vs baseline: 1.2765x; 1.0867x over previous
#include <cuda_runtime.h>

#define N_NODES 50000
#define N_EDGES 500000
#define N_GRAPHS 2000
#define HID 145
#define PITCH 148          // row pitch (16B multiple: 148*4 = 592)
#define NCH 37             // float4 chunks per row
#define WSP 160            // Ws shared pitch: 80 col-pairs
#define HID2 72
#define N_LAYERS 4
#define EPS 1e-5f
#define TILE_M 64

// ---- scratch (static device globals) ----
__device__ __align__(16) float  g_h  [(size_t)N_NODES * PITCH + 64];
__device__ __align__(16) float  g_hw [(size_t)N_NODES * PITCH];
__device__ __align__(16) float  g_agg[(size_t)N_NODES * PITCH];
__device__ float  g_dis[N_NODES];
__device__ int    g_deg[N_NODES];
__device__ int    g_rowptr[N_NODES + 1];
__device__ int    g_cursor[N_NODES];
__device__ int    g_csr_src[N_EDGES];
__device__ float  g_csr_w[N_EDGES];
__device__ double g_stats[2 * PITCH];
__device__ float  g_bnA[PITCH];
__device__ float  g_bnB[PITCH];

// packed f32x2 FMA (PTX-only; ptxas never auto-fuses)
__device__ __forceinline__ float2 ffma2(float2 a, float2 b, float2 c) {
    unsigned long long ua, ub, uc, ud;
    ua = *reinterpret_cast<unsigned long long*>(&a);
    ub = *reinterpret_cast<unsigned long long*>(&b);
    uc = *reinterpret_cast<unsigned long long*>(&c);
    asm("fma.rn.f32x2 %0, %1, %2, %3;" : "=l"(ud) : "l"(ua), "l"(ub), "l"(uc));
    return *reinterpret_cast<float2*>(&ud);
}

// ---------------- degree / CSR build ----------------
__global__ void k_deg_zero() {
    int i = blockIdx.x * blockDim.x + threadIdx.x;
    if (i < N_NODES) g_deg[i] = 0;
}

__global__ void k_deg_count(const int* __restrict__ ei) {
    int e = blockIdx.x * blockDim.x + threadIdx.x;
    if (e < N_EDGES) atomicAdd(&g_deg[ei[N_EDGES + e]], 1);  // target = col
}

__global__ void k_dis() {
    int i = blockIdx.x * blockDim.x + threadIdx.x;
    if (i < N_NODES) g_dis[i] = rsqrtf((float)(g_deg[i] + 1));  // +1 self loop
}

// single-block inclusive scan over degrees -> rowptr (exclusive), cursor copy
__global__ void k_scan() {
    __shared__ int sh[1024];
    __shared__ int carry;
    const int tid = threadIdx.x;
    if (tid == 0) carry = 0;
    __syncthreads();
    for (int base = 0; base < N_NODES; base += 1024) {
        int i = base + tid;
        int v = (i < N_NODES) ? g_deg[i] : 0;
        sh[tid] = v;
        __syncthreads();
        for (int off = 1; off < 1024; off <<= 1) {
            int t = (tid >= off) ? sh[tid - off] : 0;
            __syncthreads();
            sh[tid] += t;
            __syncthreads();
        }
        int excl = sh[tid] - v + carry;
        if (i < N_NODES) { g_rowptr[i] = excl; g_cursor[i] = excl; }
        __syncthreads();
        if (tid == 1023) carry += sh[1023];
        __syncthreads();
    }
    if (tid == 0) g_rowptr[N_NODES] = N_EDGES;
}

__global__ void k_fill(const int* __restrict__ ei) {
    int e = blockIdx.x * blockDim.x + threadIdx.x;
    if (e >= N_EDGES) return;
    int r = ei[e];
    int c = ei[N_EDGES + e];
    int pos = atomicAdd(&g_cursor[c], 1);
    g_csr_src[pos] = r;
    g_csr_w[pos]   = g_dis[r] * g_dis[c];
}

// ---------------- embedding gather ----------------
__global__ void k_embed(const int* __restrict__ x, const float* __restrict__ emb) {
    int idx = blockIdx.x * blockDim.x + threadIdx.x;
    if (idx >= N_NODES * PITCH) return;
    int i = idx / PITCH, c = idx - i * PITCH;
    g_h[idx] = (c < HID) ? emb[x[i] * HID + c] : 0.0f;
}

// ---------------- GEMM: hw = h @ Wc[l] (f32x2 packed) ----------------
__global__ void __launch_bounds__(256) k_gemm(const float* __restrict__ Wl) {
    __shared__ float As[TILE_M * 32];
    __shared__ float Ws[32 * WSP];
    const int tid  = threadIdx.x;
    const int ct   = tid & 15;
    const int rt   = tid >> 4;
    const int row0 = blockIdx.x * TILE_M;

    if (blockIdx.x == 0)
        for (int i = tid; i < 2 * PITCH; i += 256) g_stats[i] = 0.0;

    float2 acc[4][5];
#pragma unroll
    for (int r = 0; r < 4; r++)
#pragma unroll
        for (int j = 0; j < 5; j++) acc[r][j] = make_float2(0.0f, 0.0f);

    for (int kt = 0; kt < HID; kt += 32) {
        __syncthreads();
#pragma unroll
        for (int q = 0; q < 2; q++) {
            int fi  = tid + 256 * q;
            int row = fi >> 3;
            int kq  = fi & 7;
            float4 v = make_float4(0.f, 0.f, 0.f, 0.f);
            int r = row0 + row;
            if (r < N_NODES)
                v = *(const float4*)&g_h[(size_t)r * PITCH + kt + kq * 4];
            *(float4*)&As[row * 32 + kq * 4] = v;
        }
        for (int i = tid; i < 32 * WSP; i += 256) {
            int kk = i / WSP, c = i - kk * WSP;
            int kg = kt + kk;
            Ws[i] = (kg < HID && c < HID) ? Wl[kg * HID + c] : 0.0f;
        }
        __syncthreads();

#pragma unroll 4
        for (int k = 0; k < 32; k++) {
            float2 b[5];
#pragma unroll
            for (int j = 0; j < 5; j++)
                b[j] = *(const float2*)&Ws[k * WSP + 2 * ct + 32 * j];
            float a0 = As[(rt * 4 + 0) * 32 + k];
            float a1 = As[(rt * 4 + 1) * 32 + k];
            float a2 = As[(rt * 4 + 2) * 32 + k];
            float a3 = As[(rt * 4 + 3) * 32 + k];
            float2 p0 = make_float2(a0, a0), p1 = make_float2(a1, a1);
            float2 p2 = make_float2(a2, a2), p3 = make_float2(a3, a3);
#pragma unroll
            for (int j = 0; j < 5; j++) {
                acc[0][j] = ffma2(p0, b[j], acc[0][j]);
                acc[1][j] = ffma2(p1, b[j], acc[1][j]);
                acc[2][j] = ffma2(p2, b[j], acc[2][j]);
                acc[3][j] = ffma2(p3, b[j], acc[3][j]);
            }
        }
    }

#pragma unroll
    for (int rr = 0; rr < 4; rr++) {
        int r = row0 + rt * 4 + rr;
        if (r >= N_NODES) continue;
#pragma unroll
        for (int j = 0; j < 5; j++) {
            int c0 = 2 * ct + 32 * j;
            if (c0 >= PITCH) continue;
            *(float2*)&g_hw[(size_t)r * PITCH + c0] = acc[rr][j];
        }
    }
}

// ---------------- aggregation: warp-per-node CSR gather (no atomics) ---------
__global__ void __launch_bounds__(256) k_gather(const float* __restrict__ bcl) {
    int warp = (blockIdx.x * blockDim.x + threadIdx.x) >> 5;
    int lane = threadIdx.x & 31;
    if (warp >= N_NODES) return;

    const int beg = g_rowptr[warp];
    const int end = g_rowptr[warp + 1];
    float d  = g_dis[warp];
    float sw = d * d;                 // self-loop weight

    const float4* own = (const float4*)g_hw + (size_t)warp * NCH;

    // init: bias + self-loop
    float4 a0, a1 = make_float4(0.f, 0.f, 0.f, 0.f);
    {
        float4 v = own[lane];
        int c = lane * 4;             // <= 127, always valid bias range
        a0.x = bcl[c]     + sw * v.x;
        a0.y = bcl[c + 1] + sw * v.y;
        a0.z = bcl[c + 2] + sw * v.z;
        a0.w = bcl[c + 3] + sw * v.w;
        if (lane < NCH - 32) {
            float4 v2 = own[32 + lane];
            int c2 = 128 + lane * 4;
            a1.x = (c2     < HID ? bcl[c2]     : 0.0f) + sw * v2.x;
            a1.y = (c2 + 1 < HID ? bcl[c2 + 1] : 0.0f) + sw * v2.y;
            a1.z = (c2 + 2 < HID ? bcl[c2 + 2] : 0.0f) + sw * v2.z;
            a1.w = (c2 + 3 < HID ? bcl[c2 + 3] : 0.0f) + sw * v2.w;
        }
    }

    int e = beg;
    for (; e + 1 < end; e += 2) {     // 2x unroll for MLP
        int   s0 = g_csr_src[e],     s1 = g_csr_src[e + 1];
        float w0 = g_csr_w[e],       w1 = g_csr_w[e + 1];
        const float4* sp0 = (const float4*)g_hw + (size_t)s0 * NCH;
        const float4* sp1 = (const float4*)g_hw + (size_t)s1 * NCH;
        float4 v0 = sp0[lane], v1 = sp1[lane];
        a0.x += w0 * v0.x + w1 * v1.x;
        a0.y += w0 * v0.y + w1 * v1.y;
        a0.z += w0 * v0.z + w1 * v1.z;
        a0.w += w0 * v0.w + w1 * v1.w;
        if (lane < NCH - 32) {
            float4 u0 = sp0[32 + lane], u1 = sp1[32 + lane];
            a1.x += w0 * u0.x + w1 * u1.x;
            a1.y += w0 * u0.y + w1 * u1.y;
            a1.z += w0 * u0.z + w1 * u1.z;
            a1.w += w0 * u0.w + w1 * u1.w;
        }
    }
    if (e < end) {
        int   s0 = g_csr_src[e];
        float w0 = g_csr_w[e];
        const float4* sp0 = (const float4*)g_hw + (size_t)s0 * NCH;
        float4 v0 = sp0[lane];
        a0.x += w0 * v0.x; a0.y += w0 * v0.y; a0.z += w0 * v0.z; a0.w += w0 * v0.w;
        if (lane < NCH - 32) {
            float4 u0 = sp0[32 + lane];
            a1.x += w0 * u0.x; a1.y += w0 * u0.y; a1.z += w0 * u0.z; a1.w += w0 * u0.w;
        }
    }

    float4* dst = (float4*)g_agg + (size_t)warp * NCH;
    dst[lane] = a0;
    if (lane < NCH - 32) dst[32 + lane] = a1;
}

// ---------------- batchnorm stats (double partials + double atomics) ----------
#define STAT_BLOCKS 250
#define ROWS_PER_STAT ((N_NODES + STAT_BLOCKS - 1) / STAT_BLOCKS)
__global__ void k_stats() {
    int c = threadIdx.x;
    if (c >= HID) return;
    int r0 = blockIdx.x * ROWS_PER_STAT;
    int r1 = r0 + ROWS_PER_STAT; if (r1 > N_NODES) r1 = N_NODES;
    double s1 = 0.0, s2 = 0.0;
    for (int r = r0; r < r1; r++) {
        double v = (double)g_agg[(size_t)r * PITCH + c];
        s1 += v; s2 += v * v;
    }
    atomicAdd(&g_stats[c], s1);
    atomicAdd(&g_stats[PITCH + c], s2);
}

__global__ void k_bnab(const float* __restrict__ gammal, const float* __restrict__ betal) {
    int c = threadIdx.x;
    if (c >= PITCH) return;
    if (c < HID) {
        double mu  = g_stats[c] / (double)N_NODES;
        double var = g_stats[PITCH + c] / (double)N_NODES - mu * mu;
        if (var < 0.0) var = 0.0;
        float a = gammal[c] * rsqrtf((float)var + EPS);
        g_bnA[c] = a;
        g_bnB[c] = betal[c] - (float)mu * a;
    } else {
        g_bnA[c] = 0.0f;
        g_bnB[c] = 0.0f;
    }
}

// ---------------- BN apply + ReLU + residual (in place on g_h) ----------------
__global__ void k_apply() {
    int idx = blockIdx.x * blockDim.x + threadIdx.x;
    if (idx >= N_NODES * PITCH) return;
    int c = idx % PITCH;
    float v = fmaxf(g_agg[idx] * g_bnA[c] + g_bnB[c], 0.0f) + g_h[idx];
    g_h[idx] = v;
}

// ---------------- global mean pool + MLP head, one block per graph -----------
__global__ void k_pool(const int* __restrict__ batch,
                       const float* __restrict__ W1, const float* __restrict__ b1,
                       const float* __restrict__ W2, const float* __restrict__ b2,
                       float* __restrict__ out) {
    const int g   = blockIdx.x;
    const int tid = threadIdx.x;
    __shared__ float hg[HID];
    __shared__ float p[HID2];

    int lo, hi;
    { int a = 0, b = N_NODES;
      while (a < b) { int m = (a + b) >> 1; if (batch[m] < g) a = m + 1; else b = m; }
      lo = a; }
    { int a = lo, b = N_NODES;
      while (a < b) { int m = (a + b) >> 1; if (batch[m] < g + 1) a = m + 1; else b = m; }
      hi = a; }
    int cnt = hi - lo;
    float inv = 1.0f / (float)(cnt > 1 ? cnt : 1);

    if (tid < HID) {
        float s = 0.0f;
        for (int r = lo; r < hi; r++) s += g_h[(size_t)r * PITCH + tid];
        hg[tid] = s * inv;
    }
    __syncthreads();
    if (tid < HID2) {
        float s = b1[tid];
        for (int k = 0; k < HID; k++) s += hg[k] * W1[k * HID2 + tid];
        p[tid] = fmaxf(s, 0.0f) * W2[tid];
    }
    __syncthreads();
    if (tid == 0) {
        float s = b2[0];
        for (int j = 0; j < HID2; j++) s += p[j];
        out[g] = s;
    }
}

// ---------------- launch ----------------
extern "C" void kernel_launch(void* const* d_in, const int* in_sizes, int n_in,
                              void* d_out, int out_size) {
    const int*   x     = (const int*)  d_in[0];
    const int*   ei    = (const int*)  d_in[1];
    const int*   batch = (const int*)  d_in[2];
    const float* emb   = (const float*)d_in[3];
    const float* Wc    = (const float*)d_in[4];
    const float* bc    = (const float*)d_in[5];
    const float* gamma = (const float*)d_in[6];
    const float* beta  = (const float*)d_in[7];
    const float* W1    = (const float*)d_in[8];
    const float* b1    = (const float*)d_in[9];
    const float* W2    = (const float*)d_in[10];
    const float* b2    = (const float*)d_in[11];
    float* out = (float*)d_out;

    const int elemBlocks   = (N_NODES * PITCH + 255) / 256;
    const int gemmBlocks   = (N_NODES + TILE_M - 1) / TILE_M;
    const int gatherBlocks = (N_NODES * 32 + 255) / 256;

    k_deg_zero <<<(N_NODES + 255) / 256, 256>>>();
    k_deg_count<<<(N_EDGES + 255) / 256, 256>>>(ei);
    k_dis      <<<(N_NODES + 255) / 256, 256>>>();
    k_scan     <<<1, 1024>>>();
    k_fill     <<<(N_EDGES + 255) / 256, 256>>>(ei);
    k_embed    <<<elemBlocks, 256>>>(x, emb);

    for (int l = 0; l < N_LAYERS; l++) {
        k_gemm   <<<gemmBlocks, 256>>>(Wc + (size_t)l * HID * HID);
        k_gather <<<gatherBlocks, 256>>>(bc + l * HID);
        k_stats  <<<STAT_BLOCKS, 160>>>();
        k_bnab   <<<1, 160>>>(gamma + l * HID, beta + l * HID);
        k_apply  <<<elemBlocks, 256>>>();
    }

    k_pool<<<N_GRAPHS, 160>>>(batch, W1, b1, W2, b2, out);
}

// round 6
// speedup vs baseline: 1.4095x; 1.1042x over previous
#include <cuda_runtime.h>

#define N_NODES 50000
#define N_EDGES 500000
#define N_GRAPHS 2000
#define HID 145
#define PITCH 148          // row pitch (16B multiple: 148*4 = 592)
#define NCH 37             // float4 chunks per row
#define WSP 160            // Ws shared pitch: 80 col-pairs
#define HID2 72
#define N_LAYERS 4
#define EPS 1e-5f
#define TILE_M 64
#define SCAN_NB 49         // ceil(50000/1024)

// ---- scratch (static device globals) ----
__device__ __align__(16) float  g_h  [(size_t)N_NODES * PITCH + 64];
__device__ __align__(16) float  g_hw [(size_t)N_NODES * PITCH];
__device__ __align__(16) float  g_agg[(size_t)N_NODES * PITCH];
__device__ float  g_dis[N_NODES];
__device__ int    g_deg[N_NODES];
__device__ int    g_rowptr[N_NODES + 1];
__device__ int    g_cursor[N_NODES];
__device__ int    g_bsum[64];
__device__ int    g_csr_src[N_EDGES];
__device__ float  g_csr_w[N_EDGES];
__device__ double g_stats[2 * PITCH];
__device__ float  g_bnA[PITCH];
__device__ float  g_bnB[PITCH];

// packed f32x2 FMA (PTX-only; ptxas never auto-fuses)
__device__ __forceinline__ float2 ffma2(float2 a, float2 b, float2 c) {
    unsigned long long ua, ub, uc, ud;
    ua = *reinterpret_cast<unsigned long long*>(&a);
    ub = *reinterpret_cast<unsigned long long*>(&b);
    uc = *reinterpret_cast<unsigned long long*>(&c);
    asm("fma.rn.f32x2 %0, %1, %2, %3;" : "=l"(ud) : "l"(ua), "l"(ub), "l"(uc));
    return *reinterpret_cast<float2*>(&ud);
}

// ---------------- degree / CSR build ----------------
__global__ void k_deg_zero() {
    int i = blockIdx.x * blockDim.x + threadIdx.x;
    if (i < N_NODES) g_deg[i] = 0;
}

__global__ void k_deg_count(const int* __restrict__ ei) {
    int e = blockIdx.x * blockDim.x + threadIdx.x;
    if (e < N_EDGES) atomicAdd(&g_deg[ei[N_EDGES + e]], 1);  // target = col
}

__global__ void k_dis() {
    int i = blockIdx.x * blockDim.x + threadIdx.x;
    if (i < N_NODES) g_dis[i] = rsqrtf((float)(g_deg[i] + 1));  // +1 self loop
}

// ---- 3-phase parallel scan over degrees -> rowptr (exclusive), cursor ----
__global__ void k_scan1() {
    __shared__ int wsum[32];
    const int tid = threadIdx.x;
    const int i = blockIdx.x * 1024 + tid;
    int v = (i < N_NODES) ? g_deg[i] : 0;
    int lane = tid & 31, w = tid >> 5;
    int s = v;
#pragma unroll
    for (int o = 1; o < 32; o <<= 1) {
        int t = __shfl_up_sync(0xFFFFFFFFu, s, o);
        if (lane >= o) s += t;
    }
    if (lane == 31) wsum[w] = s;
    __syncthreads();
    if (w == 0) {
        int t = wsum[lane];
#pragma unroll
        for (int o = 1; o < 32; o <<= 1) {
            int u = __shfl_up_sync(0xFFFFFFFFu, t, o);
            if (lane >= o) t += u;
        }
        wsum[lane] = t;
    }
    __syncthreads();
    int excl = s - v + (w > 0 ? wsum[w - 1] : 0);
    if (i < N_NODES) g_rowptr[i] = excl;
    if (tid == 1023) g_bsum[blockIdx.x] = excl + v;   // block total
}

__global__ void k_scan2() {
    __shared__ int sh[64];
    int tid = threadIdx.x;
    if (tid < SCAN_NB) sh[tid] = g_bsum[tid];
    __syncthreads();
    if (tid == 0) {
        int acc = 0;
        for (int b = 0; b < SCAN_NB; b++) { int t = sh[b]; sh[b] = acc; acc += t; }
    }
    __syncthreads();
    if (tid < SCAN_NB) g_bsum[tid] = sh[tid];
}

__global__ void k_scan3() {
    int i = blockIdx.x * 1024 + threadIdx.x;
    if (i < N_NODES) {
        int v = g_rowptr[i] + g_bsum[blockIdx.x];
        g_rowptr[i] = v;
        g_cursor[i] = v;
    }
    if (i == 0) g_rowptr[N_NODES] = N_EDGES;
}

__global__ void k_fill(const int* __restrict__ ei) {
    int e = blockIdx.x * blockDim.x + threadIdx.x;
    if (e >= N_EDGES) return;
    int r = ei[e];
    int c = ei[N_EDGES + e];
    int pos = atomicAdd(&g_cursor[c], 1);
    g_csr_src[pos] = r;
    g_csr_w[pos]   = g_dis[r] * g_dis[c];
}

// ---------------- embedding gather ----------------
__global__ void k_embed(const int* __restrict__ x, const float* __restrict__ emb) {
    int idx = blockIdx.x * blockDim.x + threadIdx.x;
    if (idx >= N_NODES * PITCH) return;
    int i = idx / PITCH, c = idx - i * PITCH;
    g_h[idx] = (c < HID) ? emb[x[i] * HID + c] : 0.0f;
}

// ---------------- GEMM: hw = h @ Wc[l] (f32x2 packed) ----------------
__global__ void __launch_bounds__(256) k_gemm(const float* __restrict__ Wl) {
    __shared__ float As[TILE_M * 32];
    __shared__ float Ws[32 * WSP];
    const int tid  = threadIdx.x;
    const int ct   = tid & 15;
    const int rt   = tid >> 4;
    const int row0 = blockIdx.x * TILE_M;

    if (blockIdx.x == 0)
        for (int i = tid; i < 2 * PITCH; i += 256) g_stats[i] = 0.0;  // zero BN stats

    float2 acc[4][5];
#pragma unroll
    for (int r = 0; r < 4; r++)
#pragma unroll
        for (int j = 0; j < 5; j++) acc[r][j] = make_float2(0.0f, 0.0f);

    for (int kt = 0; kt < HID; kt += 32) {
        __syncthreads();
#pragma unroll
        for (int q = 0; q < 2; q++) {
            int fi  = tid + 256 * q;
            int row = fi >> 3;
            int kq  = fi & 7;
            float4 v = make_float4(0.f, 0.f, 0.f, 0.f);
            int r = row0 + row;
            if (r < N_NODES)
                v = *(const float4*)&g_h[(size_t)r * PITCH + kt + kq * 4];
            *(float4*)&As[row * 32 + kq * 4] = v;
        }
        for (int i = tid; i < 32 * WSP; i += 256) {
            int kk = i / WSP, c = i - kk * WSP;
            int kg = kt + kk;
            Ws[i] = (kg < HID && c < HID) ? Wl[kg * HID + c] : 0.0f;
        }
        __syncthreads();

#pragma unroll 4
        for (int k = 0; k < 32; k++) {
            float2 b[5];
#pragma unroll
            for (int j = 0; j < 5; j++)
                b[j] = *(const float2*)&Ws[k * WSP + 2 * ct + 32 * j];
            float a0 = As[(rt * 4 + 0) * 32 + k];
            float a1 = As[(rt * 4 + 1) * 32 + k];
            float a2 = As[(rt * 4 + 2) * 32 + k];
            float a3 = As[(rt * 4 + 3) * 32 + k];
            float2 p0 = make_float2(a0, a0), p1 = make_float2(a1, a1);
            float2 p2 = make_float2(a2, a2), p3 = make_float2(a3, a3);
#pragma unroll
            for (int j = 0; j < 5; j++) {
                acc[0][j] = ffma2(p0, b[j], acc[0][j]);
                acc[1][j] = ffma2(p1, b[j], acc[1][j]);
                acc[2][j] = ffma2(p2, b[j], acc[2][j]);
                acc[3][j] = ffma2(p3, b[j], acc[3][j]);
            }
        }
    }

#pragma unroll
    for (int rr = 0; rr < 4; rr++) {
        int r = row0 + rt * 4 + rr;
        if (r >= N_NODES) continue;
#pragma unroll
        for (int j = 0; j < 5; j++) {
            int c0 = 2 * ct + 32 * j;
            if (c0 >= PITCH) continue;
            *(float2*)&g_hw[(size_t)r * PITCH + c0] = acc[rr][j];
        }
    }
}

// ------- aggregation: warp-per-node CSR gather + fused BN stats ----------
// 512 threads = 16 warps = 16 nodes per block; 3125 blocks exactly.
__global__ void __launch_bounds__(512) k_gather(const float* __restrict__ bcl) {
    __shared__ float sums[16][PITCH];
    const int wib  = threadIdx.x >> 5;
    const int lane = threadIdx.x & 31;
    const int node = blockIdx.x * 16 + wib;     // always < N_NODES (exact grid)

    const int beg = g_rowptr[node];
    const int end = g_rowptr[node + 1];
    float d  = g_dis[node];
    float sw = d * d;                 // self-loop weight

    const float4* own = (const float4*)g_hw + (size_t)node * NCH;

    float4 a0, a1 = make_float4(0.f, 0.f, 0.f, 0.f);
    {
        float4 v = own[lane];
        int c = lane * 4;
        a0.x = bcl[c]     + sw * v.x;
        a0.y = bcl[c + 1] + sw * v.y;
        a0.z = bcl[c + 2] + sw * v.z;
        a0.w = bcl[c + 3] + sw * v.w;
        if (lane < NCH - 32) {
            float4 v2 = own[32 + lane];
            int c2 = 128 + lane * 4;
            a1.x = (c2     < HID ? bcl[c2]     : 0.0f) + sw * v2.x;
            a1.y = (c2 + 1 < HID ? bcl[c2 + 1] : 0.0f) + sw * v2.y;
            a1.z = (c2 + 2 < HID ? bcl[c2 + 2] : 0.0f) + sw * v2.z;
            a1.w = (c2 + 3 < HID ? bcl[c2 + 3] : 0.0f) + sw * v2.w;
        }
    }

    int e = beg;
    for (; e + 1 < end; e += 2) {
        int   s0 = g_csr_src[e],     s1 = g_csr_src[e + 1];
        float w0 = g_csr_w[e],       w1 = g_csr_w[e + 1];
        const float4* sp0 = (const float4*)g_hw + (size_t)s0 * NCH;
        const float4* sp1 = (const float4*)g_hw + (size_t)s1 * NCH;
        float4 v0 = sp0[lane], v1 = sp1[lane];
        a0.x += w0 * v0.x + w1 * v1.x;
        a0.y += w0 * v0.y + w1 * v1.y;
        a0.z += w0 * v0.z + w1 * v1.z;
        a0.w += w0 * v0.w + w1 * v1.w;
        if (lane < NCH - 32) {
            float4 u0 = sp0[32 + lane], u1 = sp1[32 + lane];
            a1.x += w0 * u0.x + w1 * u1.x;
            a1.y += w0 * u0.y + w1 * u1.y;
            a1.z += w0 * u0.z + w1 * u1.z;
            a1.w += w0 * u0.w + w1 * u1.w;
        }
    }
    if (e < end) {
        int   s0 = g_csr_src[e];
        float w0 = g_csr_w[e];
        const float4* sp0 = (const float4*)g_hw + (size_t)s0 * NCH;
        float4 v0 = sp0[lane];
        a0.x += w0 * v0.x; a0.y += w0 * v0.y; a0.z += w0 * v0.z; a0.w += w0 * v0.w;
        if (lane < NCH - 32) {
            float4 u0 = sp0[32 + lane];
            a1.x += w0 * u0.x; a1.y += w0 * u0.y; a1.z += w0 * u0.z; a1.w += w0 * u0.w;
        }
    }

    float4* dst = (float4*)g_agg + (size_t)node * NCH;
    dst[lane] = a0;
    if (lane < NCH - 32) dst[32 + lane] = a1;

    // stage row values for block-level BN stats
    {
        int c = lane * 4;
        sums[wib][c]     = a0.x;
        sums[wib][c + 1] = a0.y;
        sums[wib][c + 2] = a0.z;
        sums[wib][c + 3] = a0.w;
        if (lane < NCH - 32) {
            int c2 = 128 + lane * 4;
            sums[wib][c2]     = a1.x;
            sums[wib][c2 + 1] = a1.y;
            sums[wib][c2 + 2] = a1.z;
            sums[wib][c2 + 3] = a1.w;
        }
    }
    __syncthreads();
    int c = threadIdx.x;
    if (c < PITCH) {
        double s1 = 0.0, s2 = 0.0;
#pragma unroll
        for (int k = 0; k < 16; k++) {
            double v = (double)sums[k][c];
            s1 += v; s2 += v * v;
        }
        atomicAdd(&g_stats[c], s1);
        atomicAdd(&g_stats[PITCH + c], s2);
    }
}

__global__ void k_bnab(const float* __restrict__ gammal, const float* __restrict__ betal) {
    int c = threadIdx.x;
    if (c >= PITCH) return;
    if (c < HID) {
        double mu  = g_stats[c] / (double)N_NODES;
        double var = g_stats[PITCH + c] / (double)N_NODES - mu * mu;
        if (var < 0.0) var = 0.0;
        float a = gammal[c] * rsqrtf((float)var + EPS);
        g_bnA[c] = a;
        g_bnB[c] = betal[c] - (float)mu * a;
    } else {
        g_bnA[c] = 0.0f;
        g_bnB[c] = 0.0f;
    }
}

// ---------------- BN apply + ReLU + residual (in place on g_h) ----------------
__global__ void k_apply() {
    int idx = blockIdx.x * blockDim.x + threadIdx.x;
    if (idx >= N_NODES * PITCH) return;
    int c = idx % PITCH;
    float v = fmaxf(g_agg[idx] * g_bnA[c] + g_bnB[c], 0.0f) + g_h[idx];
    g_h[idx] = v;
}

// ---------------- global mean pool + MLP head, one block per graph -----------
__global__ void k_pool(const int* __restrict__ batch,
                       const float* __restrict__ W1, const float* __restrict__ b1,
                       const float* __restrict__ W2, const float* __restrict__ b2,
                       float* __restrict__ out) {
    const int g   = blockIdx.x;
    const int tid = threadIdx.x;
    __shared__ float hg[HID];
    __shared__ float p[HID2];

    int lo, hi;
    { int a = 0, b = N_NODES;
      while (a < b) { int m = (a + b) >> 1; if (batch[m] < g) a = m + 1; else b = m; }
      lo = a; }
    { int a = lo, b = N_NODES;
      while (a < b) { int m = (a + b) >> 1; if (batch[m] < g + 1) a = m + 1; else b = m; }
      hi = a; }
    int cnt = hi - lo;
    float inv = 1.0f / (float)(cnt > 1 ? cnt : 1);

    if (tid < HID) {
        float s = 0.0f;
        for (int r = lo; r < hi; r++) s += g_h[(size_t)r * PITCH + tid];
        hg[tid] = s * inv;
    }
    __syncthreads();
    if (tid < HID2) {
        float s = b1[tid];
        for (int k = 0; k < HID; k++) s += hg[k] * W1[k * HID2 + tid];
        p[tid] = fmaxf(s, 0.0f) * W2[tid];
    }
    __syncthreads();
    if (tid == 0) {
        float s = b2[0];
        for (int j = 0; j < HID2; j++) s += p[j];
        out[g] = s;
    }
}

// ---------------- launch ----------------
extern "C" void kernel_launch(void* const* d_in, const int* in_sizes, int n_in,
                              void* d_out, int out_size) {
    const int*   x     = (const int*)  d_in[0];
    const int*   ei    = (const int*)  d_in[1];
    const int*   batch = (const int*)  d_in[2];
    const float* emb   = (const float*)d_in[3];
    const float* Wc    = (const float*)d_in[4];
    const float* bc    = (const float*)d_in[5];
    const float* gamma = (const float*)d_in[6];
    const float* beta  = (const float*)d_in[7];
    const float* W1    = (const float*)d_in[8];
    const float* b1    = (const float*)d_in[9];
    const float* W2    = (const float*)d_in[10];
    const float* b2    = (const float*)d_in[11];
    float* out = (float*)d_out;

    const int elemBlocks   = (N_NODES * PITCH + 255) / 256;
    const int gemmBlocks   = (N_NODES + TILE_M - 1) / TILE_M;
    const int gatherBlocks = N_NODES / 16;   // 3125, exact

    k_deg_zero <<<(N_NODES + 255) / 256, 256>>>();
    k_deg_count<<<(N_EDGES + 255) / 256, 256>>>(ei);
    k_dis      <<<(N_NODES + 255) / 256, 256>>>();
    k_scan1    <<<SCAN_NB, 1024>>>();
    k_scan2    <<<1, 64>>>();
    k_scan3    <<<SCAN_NB, 1024>>>();
    k_fill     <<<(N_EDGES + 255) / 256, 256>>>(ei);
    k_embed    <<<elemBlocks, 256>>>(x, emb);

    for (int l = 0; l < N_LAYERS; l++) {
        k_gemm   <<<gemmBlocks, 256>>>(Wc + (size_t)l * HID * HID);
        k_gather <<<gatherBlocks, 512>>>(bc + l * HID);
        k_bnab   <<<1, 160>>>(gamma + l * HID, beta + l * HID);
        k_apply  <<<elemBlocks, 256>>>();
    }

    k_pool<<<N_GRAPHS, 160>>>(batch, W1, b1, W2, b2, out);
}

// round 7
// speedup vs baseline: 1.5002x; 1.0644x over previous
#include <cuda_runtime.h>

#define N_NODES 50000
#define N_EDGES 500000
#define N_GRAPHS 2000
#define HID 145
#define PITCH 148          // row pitch (16B multiple: 148*4 = 592)
#define NCH 37             // float4 chunks per row
#define WSP 160            // Ws shared pitch: 80 col-pairs
#define HID2 72
#define N_LAYERS 4
#define EPS 1e-5f
#define TILE_M 64
#define SCAN_NB 49         // ceil(50000/1024)

// ---- scratch (static device globals; +64 pad for overhung tile loads) ----
__device__ __align__(16) float  g_h  [(size_t)N_NODES * PITCH + 64];
__device__ __align__(16) float  g_hw [(size_t)N_NODES * PITCH + 64];
__device__ __align__(16) float  g_agg[(size_t)N_NODES * PITCH + 64];
__device__ float  g_dis[N_NODES];
__device__ int    g_deg[N_NODES];
__device__ int    g_rowptr[N_NODES + 1];
__device__ int    g_cursor[N_NODES];
__device__ int    g_bsum[64];
__device__ int    g_csr_src[N_EDGES];
__device__ float  g_csr_w[N_EDGES];
__device__ double g_stats[2 * PITCH];
__device__ __align__(16) float g_bnA[160];
__device__ __align__(16) float g_bnB[160];

// packed f32x2 FMA (PTX-only; ptxas never auto-fuses)
__device__ __forceinline__ float2 ffma2(float2 a, float2 b, float2 c) {
    unsigned long long ua, ub, uc, ud;
    ua = *reinterpret_cast<unsigned long long*>(&a);
    ub = *reinterpret_cast<unsigned long long*>(&b);
    uc = *reinterpret_cast<unsigned long long*>(&c);
    asm("fma.rn.f32x2 %0, %1, %2, %3;" : "=l"(ud) : "l"(ua), "l"(ub), "l"(uc));
    return *reinterpret_cast<float2*>(&ud);
}

// ---------------- degree / CSR build ----------------
__global__ void k_deg_zero() {
    int i = blockIdx.x * blockDim.x + threadIdx.x;
    if (i < N_NODES) g_deg[i] = 0;
}

__global__ void k_deg_count(const int* __restrict__ ei) {
    int e = blockIdx.x * blockDim.x + threadIdx.x;
    if (e < N_EDGES) atomicAdd(&g_deg[ei[N_EDGES + e]], 1);  // target = col
}

__global__ void k_dis() {
    int i = blockIdx.x * blockDim.x + threadIdx.x;
    if (i < N_NODES) g_dis[i] = rsqrtf((float)(g_deg[i] + 1));  // +1 self loop
}

// ---- 3-phase parallel scan over degrees -> rowptr (exclusive), cursor ----
__global__ void k_scan1() {
    __shared__ int wsum[32];
    const int tid = threadIdx.x;
    const int i = blockIdx.x * 1024 + tid;
    int v = (i < N_NODES) ? g_deg[i] : 0;
    int lane = tid & 31, w = tid >> 5;
    int s = v;
#pragma unroll
    for (int o = 1; o < 32; o <<= 1) {
        int t = __shfl_up_sync(0xFFFFFFFFu, s, o);
        if (lane >= o) s += t;
    }
    if (lane == 31) wsum[w] = s;
    __syncthreads();
    if (w == 0) {
        int t = wsum[lane];
#pragma unroll
        for (int o = 1; o < 32; o <<= 1) {
            int u = __shfl_up_sync(0xFFFFFFFFu, t, o);
            if (lane >= o) t += u;
        }
        wsum[lane] = t;
    }
    __syncthreads();
    int excl = s - v + (w > 0 ? wsum[w - 1] : 0);
    if (i < N_NODES) g_rowptr[i] = excl;
    if (tid == 1023) g_bsum[blockIdx.x] = excl + v;   // block total
}

__global__ void k_scan2() {
    __shared__ int sh[64];
    int tid = threadIdx.x;
    if (tid < SCAN_NB) sh[tid] = g_bsum[tid];
    __syncthreads();
    if (tid == 0) {
        int acc = 0;
        for (int b = 0; b < SCAN_NB; b++) { int t = sh[b]; sh[b] = acc; acc += t; }
    }
    __syncthreads();
    if (tid < SCAN_NB) g_bsum[tid] = sh[tid];
}

__global__ void k_scan3() {
    int i = blockIdx.x * 1024 + threadIdx.x;
    if (i < N_NODES) {
        int v = g_rowptr[i] + g_bsum[blockIdx.x];
        g_rowptr[i] = v;
        g_cursor[i] = v;
    }
    if (i == 0) g_rowptr[N_NODES] = N_EDGES;
}

__global__ void k_fill(const int* __restrict__ ei) {
    int e = blockIdx.x * blockDim.x + threadIdx.x;
    if (e >= N_EDGES) return;
    int r = ei[e];
    int c = ei[N_EDGES + e];
    int pos = atomicAdd(&g_cursor[c], 1);
    g_csr_src[pos] = r;
    g_csr_w[pos]   = g_dis[r] * g_dis[c];
}

// ---------------- GEMM: hw = h @ Wc[l], with fused A-generation ----------------
// mode 0: A = emb[x[row]]  (embedding gather; also materializes g_h)
// mode 1: A = relu(g_agg*bnA+bnB) + g_h_old  (prev layer's BN+ReLU+residual;
//         writes h_new back to g_h)
__global__ void __launch_bounds__(256) k_gemm(const float* __restrict__ Wl,
                                              const int*   __restrict__ x,
                                              const float* __restrict__ emb,
                                              int mode) {
    __shared__ float As[TILE_M * 32];
    __shared__ float Ws[32 * WSP];
    const int tid  = threadIdx.x;
    const int ct   = tid & 15;
    const int rt   = tid >> 4;
    const int row0 = blockIdx.x * TILE_M;

    if (blockIdx.x == 0)
        for (int i = tid; i < 2 * PITCH; i += 256) g_stats[i] = 0.0;  // zero BN stats

    float2 acc[4][5];
#pragma unroll
    for (int r = 0; r < 4; r++)
#pragma unroll
        for (int j = 0; j < 5; j++) acc[r][j] = make_float2(0.0f, 0.0f);

    for (int kt = 0; kt < HID; kt += 32) {
        __syncthreads();
#pragma unroll
        for (int q = 0; q < 2; q++) {
            int fi   = tid + 256 * q;
            int row  = fi >> 3;
            int kq   = fi & 7;
            int col0 = kt + kq * 4;
            int r    = row0 + row;
            float4 v = make_float4(0.f, 0.f, 0.f, 0.f);
            if (r < N_NODES) {
                if (mode == 0) {
                    int base = x[r] * HID;
                    v.x = (col0     < HID) ? emb[base + col0]     : 0.0f;
                    v.y = (col0 + 1 < HID) ? emb[base + col0 + 1] : 0.0f;
                    v.z = (col0 + 2 < HID) ? emb[base + col0 + 2] : 0.0f;
                    v.w = (col0 + 3 < HID) ? emb[base + col0 + 3] : 0.0f;
                    if (col0 < PITCH) *(float4*)&g_h[(size_t)r * PITCH + col0] = v;
                } else {
                    float4 va = *(const float4*)&g_agg[(size_t)r * PITCH + col0];
                    float4 vh = *(const float4*)&g_h  [(size_t)r * PITCH + col0];
                    float4 A  = *(const float4*)&g_bnA[col0];
                    float4 B  = *(const float4*)&g_bnB[col0];
                    v.x = fmaxf(va.x * A.x + B.x, 0.0f) + vh.x;
                    v.y = fmaxf(va.y * A.y + B.y, 0.0f) + vh.y;
                    v.z = fmaxf(va.z * A.z + B.z, 0.0f) + vh.z;
                    v.w = fmaxf(va.w * A.w + B.w, 0.0f) + vh.w;
                    if (col0 < PITCH) *(float4*)&g_h[(size_t)r * PITCH + col0] = v;
                }
            }
            *(float4*)&As[row * 32 + kq * 4] = v;
        }
        for (int i = tid; i < 32 * WSP; i += 256) {
            int kk = i / WSP, c = i - kk * WSP;
            int kg = kt + kk;
            Ws[i] = (kg < HID && c < HID) ? Wl[kg * HID + c] : 0.0f;
        }
        __syncthreads();

#pragma unroll 4
        for (int k = 0; k < 32; k++) {
            float2 b[5];
#pragma unroll
            for (int j = 0; j < 5; j++)
                b[j] = *(const float2*)&Ws[k * WSP + 2 * ct + 32 * j];
            float a0 = As[(rt * 4 + 0) * 32 + k];
            float a1 = As[(rt * 4 + 1) * 32 + k];
            float a2 = As[(rt * 4 + 2) * 32 + k];
            float a3 = As[(rt * 4 + 3) * 32 + k];
            float2 p0 = make_float2(a0, a0), p1 = make_float2(a1, a1);
            float2 p2 = make_float2(a2, a2), p3 = make_float2(a3, a3);
#pragma unroll
            for (int j = 0; j < 5; j++) {
                acc[0][j] = ffma2(p0, b[j], acc[0][j]);
                acc[1][j] = ffma2(p1, b[j], acc[1][j]);
                acc[2][j] = ffma2(p2, b[j], acc[2][j]);
                acc[3][j] = ffma2(p3, b[j], acc[3][j]);
            }
        }
    }

#pragma unroll
    for (int rr = 0; rr < 4; rr++) {
        int r = row0 + rt * 4 + rr;
        if (r >= N_NODES) continue;
#pragma unroll
        for (int j = 0; j < 5; j++) {
            int c0 = 2 * ct + 32 * j;
            if (c0 >= PITCH) continue;
            *(float2*)&g_hw[(size_t)r * PITCH + c0] = acc[rr][j];
        }
    }
}

// ------- aggregation: warp-per-node CSR gather + fused BN stats ----------
__global__ void __launch_bounds__(512) k_gather(const float* __restrict__ bcl) {
    __shared__ float sums[16][PITCH];
    const int wib  = threadIdx.x >> 5;
    const int lane = threadIdx.x & 31;
    const int node = blockIdx.x * 16 + wib;     // exact grid: always < N_NODES

    const int beg = g_rowptr[node];
    const int end = g_rowptr[node + 1];
    float d  = g_dis[node];
    float sw = d * d;                 // self-loop weight

    const float4* own = (const float4*)g_hw + (size_t)node * NCH;

    float4 a0, a1 = make_float4(0.f, 0.f, 0.f, 0.f);
    {
        float4 v = own[lane];
        int c = lane * 4;
        a0.x = bcl[c]     + sw * v.x;
        a0.y = bcl[c + 1] + sw * v.y;
        a0.z = bcl[c + 2] + sw * v.z;
        a0.w = bcl[c + 3] + sw * v.w;
        if (lane < NCH - 32) {
            float4 v2 = own[32 + lane];
            int c2 = 128 + lane * 4;
            a1.x = (c2     < HID ? bcl[c2]     : 0.0f) + sw * v2.x;
            a1.y = (c2 + 1 < HID ? bcl[c2 + 1] : 0.0f) + sw * v2.y;
            a1.z = (c2 + 2 < HID ? bcl[c2 + 2] : 0.0f) + sw * v2.z;
            a1.w = (c2 + 3 < HID ? bcl[c2 + 3] : 0.0f) + sw * v2.w;
        }
    }

    int e = beg;
    for (; e + 1 < end; e += 2) {
        int   s0 = g_csr_src[e],     s1 = g_csr_src[e + 1];
        float w0 = g_csr_w[e],       w1 = g_csr_w[e + 1];
        const float4* sp0 = (const float4*)g_hw + (size_t)s0 * NCH;
        const float4* sp1 = (const float4*)g_hw + (size_t)s1 * NCH;
        float4 v0 = sp0[lane], v1 = sp1[lane];
        a0.x += w0 * v0.x + w1 * v1.x;
        a0.y += w0 * v0.y + w1 * v1.y;
        a0.z += w0 * v0.z + w1 * v1.z;
        a0.w += w0 * v0.w + w1 * v1.w;
        if (lane < NCH - 32) {
            float4 u0 = sp0[32 + lane], u1 = sp1[32 + lane];
            a1.x += w0 * u0.x + w1 * u1.x;
            a1.y += w0 * u0.y + w1 * u1.y;
            a1.z += w0 * u0.z + w1 * u1.z;
            a1.w += w0 * u0.w + w1 * u1.w;
        }
    }
    if (e < end) {
        int   s0 = g_csr_src[e];
        float w0 = g_csr_w[e];
        const float4* sp0 = (const float4*)g_hw + (size_t)s0 * NCH;
        float4 v0 = sp0[lane];
        a0.x += w0 * v0.x; a0.y += w0 * v0.y; a0.z += w0 * v0.z; a0.w += w0 * v0.w;
        if (lane < NCH - 32) {
            float4 u0 = sp0[32 + lane];
            a1.x += w0 * u0.x; a1.y += w0 * u0.y; a1.z += w0 * u0.z; a1.w += w0 * u0.w;
        }
    }

    float4* dst = (float4*)g_agg + (size_t)node * NCH;
    dst[lane] = a0;
    if (lane < NCH - 32) dst[32 + lane] = a1;

    // stage row values for block-level BN stats
    {
        int c = lane * 4;
        sums[wib][c]     = a0.x;
        sums[wib][c + 1] = a0.y;
        sums[wib][c + 2] = a0.z;
        sums[wib][c + 3] = a0.w;
        if (lane < NCH - 32) {
            int c2 = 128 + lane * 4;
            sums[wib][c2]     = a1.x;
            sums[wib][c2 + 1] = a1.y;
            sums[wib][c2 + 2] = a1.z;
            sums[wib][c2 + 3] = a1.w;
        }
    }
    __syncthreads();
    int c = threadIdx.x;
    if (c < PITCH) {
        double s1 = 0.0, s2 = 0.0;
#pragma unroll
        for (int k = 0; k < 16; k++) {
            double v = (double)sums[k][c];
            s1 += v; s2 += v * v;
        }
        atomicAdd(&g_stats[c], s1);
        atomicAdd(&g_stats[PITCH + c], s2);
    }
}

__global__ void k_bnab(const float* __restrict__ gammal, const float* __restrict__ betal) {
    int c = threadIdx.x;
    if (c >= 160) return;
    if (c < HID) {
        double mu  = g_stats[c] / (double)N_NODES;
        double var = g_stats[PITCH + c] / (double)N_NODES - mu * mu;
        if (var < 0.0) var = 0.0;
        float a = gammal[c] * rsqrtf((float)var + EPS);
        g_bnA[c] = a;
        g_bnB[c] = betal[c] - (float)mu * a;
    } else {
        g_bnA[c] = 0.0f;
        g_bnB[c] = 0.0f;
    }
}

// ------- global mean pool (fused final BN apply) + MLP head -------
__global__ void k_pool(const int* __restrict__ batch,
                       const float* __restrict__ W1, const float* __restrict__ b1,
                       const float* __restrict__ W2, const float* __restrict__ b2,
                       float* __restrict__ out) {
    const int g   = blockIdx.x;
    const int tid = threadIdx.x;
    __shared__ float hg[HID];
    __shared__ float p[HID2];

    int lo, hi;
    { int a = 0, b = N_NODES;
      while (a < b) { int m = (a + b) >> 1; if (batch[m] < g) a = m + 1; else b = m; }
      lo = a; }
    { int a = lo, b = N_NODES;
      while (a < b) { int m = (a + b) >> 1; if (batch[m] < g + 1) a = m + 1; else b = m; }
      hi = a; }
    int cnt = hi - lo;
    float inv = 1.0f / (float)(cnt > 1 ? cnt : 1);

    if (tid < HID) {
        float A = g_bnA[tid], B = g_bnB[tid];
        float s = 0.0f;
        for (int r = lo; r < hi; r++) {
            size_t o = (size_t)r * PITCH + tid;
            s += fmaxf(g_agg[o] * A + B, 0.0f) + g_h[o];
        }
        hg[tid] = s * inv;
    }
    __syncthreads();
    if (tid < HID2) {
        float s = b1[tid];
        for (int k = 0; k < HID; k++) s += hg[k] * W1[k * HID2 + tid];
        p[tid] = fmaxf(s, 0.0f) * W2[tid];
    }
    __syncthreads();
    if (tid == 0) {
        float s = b2[0];
        for (int j = 0; j < HID2; j++) s += p[j];
        out[g] = s;
    }
}

// ---------------- launch ----------------
extern "C" void kernel_launch(void* const* d_in, const int* in_sizes, int n_in,
                              void* d_out, int out_size) {
    const int*   x     = (const int*)  d_in[0];
    const int*   ei    = (const int*)  d_in[1];
    const int*   batch = (const int*)  d_in[2];
    const float* emb   = (const float*)d_in[3];
    const float* Wc    = (const float*)d_in[4];
    const float* bc    = (const float*)d_in[5];
    const float* gamma = (const float*)d_in[6];
    const float* beta  = (const float*)d_in[7];
    const float* W1    = (const float*)d_in[8];
    const float* b1    = (const float*)d_in[9];
    const float* W2    = (const float*)d_in[10];
    const float* b2    = (const float*)d_in[11];
    float* out = (float*)d_out;

    const int gemmBlocks   = (N_NODES + TILE_M - 1) / TILE_M;
    const int gatherBlocks = N_NODES / 16;   // 3125, exact

    k_deg_zero <<<(N_NODES + 255) / 256, 256>>>();
    k_deg_count<<<(N_EDGES + 255) / 256, 256>>>(ei);
    k_dis      <<<(N_NODES + 255) / 256, 256>>>();
    k_scan1    <<<SCAN_NB, 1024>>>();
    k_scan2    <<<1, 64>>>();
    k_scan3    <<<SCAN_NB, 1024>>>();
    k_fill     <<<(N_EDGES + 255) / 256, 256>>>(ei);

    for (int l = 0; l < N_LAYERS; l++) {
        k_gemm   <<<gemmBlocks, 256>>>(Wc + (size_t)l * HID * HID, x, emb,
                                       l == 0 ? 0 : 1);
        k_gather <<<gatherBlocks, 512>>>(bc + l * HID);
        k_bnab   <<<1, 160>>>(gamma + l * HID, beta + l * HID);
    }

    k_pool<<<N_GRAPHS, 160>>>(batch, W1, b1, W2, b2, out);
}